// round 9
// baseline (speedup 1.0000x reference)
#include <cuda_runtime.h>
#include <cuda_fp16.h>
#include <cstdint>
#include <cstddef>

#define NN 100000
#define EE 1000000
#define DD 128
#define HH 8
#define SCALE_ATT 0.25f   // 1/sqrt(16)
#define LDS_PAD 132       // smem row stride (floats)
#define NB 98             // scan blocks of 1024 covering NN (+1)
#define TILE_R 64
#define NTILES ((NN + TILE_R - 1) / TILE_R)   // 1563
#define GEMM_GRID 296

// ---------------- scratch (static device globals) --------------------------
__device__ float   g_xt[NN * DD];      // layer-2 GEMM input (tf32, from attn1)
__device__ float   g_wt[8 * DD * DD];  // tf32-rounded, transposed weights Wt[c][k]
__device__ float   g_q[NN * DD];
__device__ __half2 g_kh[NN * DD / 2];  // fp16 k
__device__ __half2 g_vh[NN * DD / 2];  // fp16 v
__device__ float   g_skip[NN * DD];
__device__ int     g_deg[NN];
__device__ int     g_roff[NN + 1];
__device__ int     g_mut[NN];
__device__ int     g_csr[EE];
__device__ int     g_bsum[NB];
__device__ int     g_bpre[NB];

// ---- side stream + events, created at load time (before harness baseline) --
namespace {
struct SideStream {
    cudaStream_t s2 = nullptr;
    cudaEvent_t ev_fork = nullptr, ev_join = nullptr;
    SideStream() {
        cudaStreamCreateWithFlags(&s2, cudaStreamNonBlocking);
        cudaEventCreateWithFlags(&ev_fork, cudaEventDisableTiming);
        cudaEventCreateWithFlags(&ev_join, cudaEventDisableTiming);
    }
};
SideStream g_ss;
}

__device__ __forceinline__ float tf32r(float x) {
    uint32_t u;
    asm("cvt.rna.tf32.f32 %0, %1;" : "=r"(u) : "f"(x));
    return __uint_as_float(u);
}

#define CP_ASYNC16(dst_u32, src_ptr) \
    asm volatile("cp.async.cg.shared.global [%0], [%1], 16;" \
                 :: "r"(dst_u32), "l"(src_ptr))
#define CP_ASYNC_COMMIT() asm volatile("cp.async.commit_group;")
#define CP_ASYNC_WAIT0()  asm volatile("cp.async.wait_group 0;")

// ================= CSR build =================
__global__ void zero_deg_kernel() {
    int i = blockIdx.x * blockDim.x + threadIdx.x;
    if (i < NN) g_deg[i] = 0;
}

__global__ void hist_kernel(const int* __restrict__ ei) {
    int e = blockIdx.x * blockDim.x + threadIdx.x;
    if (e < EE) atomicAdd(&g_deg[ei[EE + e]], 1);
}

__global__ void csr_bsum_kernel() {
    __shared__ int sm[1024];
    int tid = threadIdx.x;
    int idx = blockIdx.x * 1024 + tid;
    sm[tid] = (idx < NN) ? g_deg[idx] : 0;
    __syncthreads();
    for (int s = 512; s > 0; s >>= 1) {
        if (tid < s) sm[tid] += sm[tid + s];
        __syncthreads();
    }
    if (tid == 0) g_bsum[blockIdx.x] = sm[0];
}

__global__ void csr_scanb_kernel() {
    __shared__ int sm[128];
    int tid = threadIdx.x;
    int v = (tid < NB) ? g_bsum[tid] : 0;
    sm[tid] = v;
    __syncthreads();
    for (int off = 1; off < 128; off <<= 1) {
        int t = (tid >= off) ? sm[tid - off] : 0;
        __syncthreads();
        sm[tid] += t;
        __syncthreads();
    }
    if (tid < NB) g_bpre[tid] = sm[tid] - v;   // exclusive
}

__global__ void csr_offsets_kernel() {
    __shared__ int sm[1024];
    int tid = threadIdx.x;
    int idx = blockIdx.x * 1024 + tid;
    int v = (idx < NN) ? g_deg[idx] : 0;
    sm[tid] = v;
    __syncthreads();
    for (int off = 1; off < 1024; off <<= 1) {
        int t = (tid >= off) ? sm[tid - off] : 0;
        __syncthreads();
        sm[tid] += t;
        __syncthreads();
    }
    int excl = sm[tid] - v + g_bpre[blockIdx.x];
    if (idx < NN) { g_roff[idx] = excl; g_mut[idx] = excl; }
    if (idx == NN) g_roff[NN] = excl;          // == EE
}

__global__ void csr_scatter_kernel(const int* __restrict__ ei) {
    int e = blockIdx.x * blockDim.x + threadIdx.x;
    if (e >= EE) return;
    int s = ei[e], d = ei[EE + e];
    int pos = atomicAdd(&g_mut[d], 1);
    g_csr[pos] = s;
}

// ================= weight prep =================
__global__ void prep_w_kernel(
    const float* __restrict__ W0, const float* __restrict__ W1,
    const float* __restrict__ W2, const float* __restrict__ W3,
    const float* __restrict__ W4, const float* __restrict__ W5,
    const float* __restrict__ W6, const float* __restrict__ W7)
{
    const float* Ws[8] = {W0, W1, W2, W3, W4, W5, W6, W7};
    int m = blockIdx.z;
    const float* W = Ws[m];
    __shared__ float t[32][33];
    int k0 = blockIdx.x * 32, c0 = blockIdx.y * 32;
    int tx = threadIdx.x, ty = threadIdx.y;
#pragma unroll
    for (int i = 0; i < 4; i++)
        t[ty + 8 * i][tx] = tf32r(W[(k0 + ty + 8 * i) * DD + c0 + tx]);
    __syncthreads();
#pragma unroll
    for (int i = 0; i < 4; i++)
        g_wt[m * DD * DD + (c0 + ty + 8 * i) * DD + k0 + tx] = t[tx][ty + 8 * i];
}

// ================= persistent merged 4-matrix tf32 GEMM =================
__global__ __launch_bounds__(256, 2) void gemm_all_kernel(
    int wofs, const float* __restrict__ X,
    const float* __restrict__ B0, const float* __restrict__ B1,
    const float* __restrict__ B2, const float* __restrict__ B3,
    float* Oq, __half2* Ok, __half2* Ov, float* Osk)
{
    extern __shared__ float smem[];
    float* Xs = smem;                       // [64][LDS_PAD]
    float* Ws = smem + TILE_R * LDS_PAD;    // [128][LDS_PAD]  W[c][k]

    const float* Bs[4] = {B0, B1, B2, B3};

    int tid = threadIdx.x;
    int warp = tid >> 5, lane = tid & 31;
    int rbase = (warp >> 2) * 32;           // {0,32}
    int cbase = (warp & 3) * 32;            // {0,32,64,96}
    int lr = lane >> 2, lk = lane & 3;

    uint32_t ws_b = (uint32_t)__cvta_generic_to_shared(Ws);

#pragma unroll 1
    for (int m = 0; m < 4; m++) {
        const float* Wt = g_wt + (size_t)(wofs + m) * DD * DD;
#pragma unroll
        for (int it = 0; it < 16; it++) {
            int i = tid + it * 256;
            int r = i >> 5, c4 = (i & 31) * 4;
            CP_ASYNC16(ws_b + (r * LDS_PAD + c4) * 4, Wt + (size_t)r * DD + c4);
        }
        CP_ASYNC_COMMIT();

        const float* B = Bs[m];
        float bb[4][2];
#pragma unroll
        for (int nt = 0; nt < 4; nt++) {
            int col = cbase + nt * 8 + 2 * lk;
            bb[nt][0] = B[col]; bb[nt][1] = B[col + 1];
        }

        CP_ASYNC_WAIT0();

        for (int t = blockIdx.x; t < NTILES; t += GEMM_GRID) {
            int row0 = t * TILE_R;
            __syncthreads();   // prior compute done (Xs safe) + W visible
#pragma unroll
            for (int it = 0; it < 8; it++) {
                int i = tid + it * 256;
                int r = i >> 5, c4 = (i & 31) * 4;
                int gr = row0 + r; if (gr >= NN) gr = NN - 1;
                float4 xv = *(const float4*)(X + (size_t)gr * DD + c4);
                float* p = Xs + r * LDS_PAD + c4;
                p[0] = tf32r(xv.x); p[1] = tf32r(xv.y);
                p[2] = tf32r(xv.z); p[3] = tf32r(xv.w);
            }
            __syncthreads();

            float acc[2][4][4];
#pragma unroll
            for (int nt = 0; nt < 4; nt++)
#pragma unroll
                for (int mt = 0; mt < 2; mt++) {
                    acc[mt][nt][0] = bb[nt][0]; acc[mt][nt][1] = bb[nt][1];
                    acc[mt][nt][2] = bb[nt][0]; acc[mt][nt][3] = bb[nt][1];
                }

#pragma unroll
            for (int ks = 0; ks < 16; ks++) {
                int k0 = ks * 8;
                uint32_t a[2][4];
#pragma unroll
                for (int mt = 0; mt < 2; mt++) {
                    const float* base = Xs + (rbase + mt * 16 + lr) * LDS_PAD + k0 + lk;
                    a[mt][0] = __float_as_uint(base[0]);
                    a[mt][1] = __float_as_uint(base[8 * LDS_PAD]);
                    a[mt][2] = __float_as_uint(base[4]);
                    a[mt][3] = __float_as_uint(base[8 * LDS_PAD + 4]);
                }
#pragma unroll
                for (int nt = 0; nt < 4; nt++) {
                    const float* bbase = Ws + (cbase + nt * 8 + lr) * LDS_PAD + k0 + lk;
                    uint32_t b0 = __float_as_uint(bbase[0]);
                    uint32_t b1 = __float_as_uint(bbase[4]);
#pragma unroll
                    for (int mt = 0; mt < 2; mt++) {
                        asm volatile(
                            "mma.sync.aligned.m16n8k8.row.col.f32.tf32.tf32.f32 "
                            "{%0,%1,%2,%3}, {%4,%5,%6,%7}, {%8,%9}, {%0,%1,%2,%3};"
                            : "+f"(acc[mt][nt][0]), "+f"(acc[mt][nt][1]),
                              "+f"(acc[mt][nt][2]), "+f"(acc[mt][nt][3])
                            : "r"(a[mt][0]), "r"(a[mt][1]), "r"(a[mt][2]), "r"(a[mt][3]),
                              "r"(b0), "r"(b1));
                    }
                }
            }

            if (m == 0 || m == 3) {
                float* O = (m == 0) ? Oq : Osk;
#pragma unroll
                for (int mt = 0; mt < 2; mt++) {
                    int gr0 = row0 + rbase + mt * 16 + lr;
                    int gr1 = gr0 + 8;
#pragma unroll
                    for (int nt = 0; nt < 4; nt++) {
                        int col = cbase + nt * 8 + 2 * lk;
                        if (gr0 < NN)
                            *(float2*)(O + (size_t)gr0 * DD + col) =
                                make_float2(acc[mt][nt][0], acc[mt][nt][1]);
                        if (gr1 < NN)
                            *(float2*)(O + (size_t)gr1 * DD + col) =
                                make_float2(acc[mt][nt][2], acc[mt][nt][3]);
                    }
                }
            } else {
                __half2* O = (m == 1) ? Ok : Ov;
#pragma unroll
                for (int mt = 0; mt < 2; mt++) {
                    int gr0 = row0 + rbase + mt * 16 + lr;
                    int gr1 = gr0 + 8;
#pragma unroll
                    for (int nt = 0; nt < 4; nt++) {
                        int col = cbase + nt * 8 + 2 * lk;
                        if (gr0 < NN)
                            O[(size_t)gr0 * (DD / 2) + (col >> 1)] =
                                __floats2half2_rn(acc[mt][nt][0], acc[mt][nt][1]);
                        if (gr1 < NN)
                            O[(size_t)gr1 * (DD / 2) + (col >> 1)] =
                                __floats2half2_rn(acc[mt][nt][2], acc[mt][nt][3]);
                    }
                }
            }
        }
        __syncthreads();   // all reads of Ws done before next m overwrites
    }
}

// ================= half-warp-per-edge attention aggregation =================
// Warp owns a node; the two 16-lane groups process alternating edges.
// Lane gl in a group covers dims [8gl, 8gl+8); head = gl>>1 (16 dims = 2 lanes).
__global__ __launch_bounds__(256) void node_attn_kernel(
    const float* __restrict__ q, const __half2* __restrict__ kh,
    const __half2* __restrict__ vh, const float* __restrict__ skip,
    const float* __restrict__ resid, const float* __restrict__ a_ptr,
    float* __restrict__ out, int do_tf32)
{
    int n = (blockIdx.x * blockDim.x + threadIdx.x) >> 5;
    if (n >= NN) return;
    int lane = threadIdx.x & 31;
    int group = lane >> 4, gl = lane & 15;
    unsigned hmask = 0xFFFFu << (group << 4);

    const float4* qrow = (const float4*)(q + (size_t)n * DD);
    float4 q0 = qrow[2 * gl], q1 = qrow[2 * gl + 1];

    int j0 = g_roff[n], j1 = g_roff[n + 1];

    float acc[8] = {0.f, 0.f, 0.f, 0.f, 0.f, 0.f, 0.f, 0.f};
    float ws = 0.f;

#pragma unroll 2
    for (int j = j0 + group; j < j1; j += 2) {
        int s = g_csr[j];
        uint4 kk = ((const uint4*)(kh + (size_t)s * (DD / 2)))[gl];
        float2 ka = __half22float2(*(const __half2*)&kk.x);
        float2 kb = __half22float2(*(const __half2*)&kk.y);
        float2 kc = __half22float2(*(const __half2*)&kk.z);
        float2 kd = __half22float2(*(const __half2*)&kk.w);
        float p = q0.x * ka.x + q0.y * ka.y + q0.z * kb.x + q0.w * kb.y
                + q1.x * kc.x + q1.y * kc.y + q1.z * kd.x + q1.w * kd.y;
        p += __shfl_xor_sync(hmask, p, 1);
        float w = __expf(p * SCALE_ATT);
        ws += w;
        uint4 vv = ((const uint4*)(vh + (size_t)s * (DD / 2)))[gl];
        float2 va = __half22float2(*(const __half2*)&vv.x);
        float2 vb = __half22float2(*(const __half2*)&vv.y);
        float2 vc = __half22float2(*(const __half2*)&vv.z);
        float2 vd = __half22float2(*(const __half2*)&vv.w);
        acc[0] += w * va.x; acc[1] += w * va.y;
        acc[2] += w * vb.x; acc[3] += w * vb.y;
        acc[4] += w * vc.x; acc[5] += w * vc.y;
        acc[6] += w * vd.x; acc[7] += w * vd.y;
    }

    __syncwarp();
    ws += __shfl_xor_sync(0xFFFFFFFFu, ws, 16);
#pragma unroll
    for (int i = 0; i < 8; i++)
        acc[i] += __shfl_xor_sync(0xFFFFFFFFu, acc[i], 16);

    if (group == 0) {
        float inv = (ws > 0.f) ? 1.f / ws : 0.f;
        const float4* skrow = (const float4*)(skip + (size_t)n * DD);
        float4 s0 = skrow[2 * gl], s1 = skrow[2 * gl + 1];
        float y[8];
        y[0] = acc[0] * inv + s0.x; y[1] = acc[1] * inv + s0.y;
        y[2] = acc[2] * inv + s0.z; y[3] = acc[3] * inv + s0.w;
        y[4] = acc[4] * inv + s1.x; y[5] = acc[5] * inv + s1.y;
        y[6] = acc[6] * inv + s1.z; y[7] = acc[7] * inv + s1.w;
        if (resid) {
            const float4* rrow = (const float4*)(resid + (size_t)n * DD);
            float4 r0 = rrow[2 * gl], r1 = rrow[2 * gl + 1];
            y[0] += r0.x; y[1] += r0.y; y[2] += r0.z; y[3] += r0.w;
            y[4] += r1.x; y[5] += r1.y; y[6] += r1.z; y[7] += r1.w;
        }
        float a = *a_ptr;
#pragma unroll
        for (int i = 0; i < 8; i++) {
            y[i] = (y[i] >= 0.f) ? y[i] : a * y[i];
            if (do_tf32) y[i] = tf32r(y[i]);
        }
        float4* orow = (float4*)(out + (size_t)n * DD);
        orow[2 * gl]     = make_float4(y[0], y[1], y[2], y[3]);
        orow[2 * gl + 1] = make_float4(y[4], y[5], y[6], y[7]);
    }
}

// ---------------- host launch ----------------------------------------------
extern "C" void kernel_launch(void* const* d_in, const int* in_sizes, int n_in,
                              void* d_out, int out_size)
{
    (void)in_sizes; (void)n_in; (void)out_size;
    const float* x   = (const float*)d_in[0];
    const int*   ei  = (const int*)d_in[1];
    const float* a   = (const float*)d_in[2];
    const float* Wq1 = (const float*)d_in[3];  const float* bq1 = (const float*)d_in[4];
    const float* Wk1 = (const float*)d_in[5];  const float* bk1 = (const float*)d_in[6];
    const float* Wv1 = (const float*)d_in[7];  const float* bv1 = (const float*)d_in[8];
    const float* Ws1 = (const float*)d_in[9];  const float* bs1 = (const float*)d_in[10];
    const float* Wq2 = (const float*)d_in[11]; const float* bq2 = (const float*)d_in[12];
    const float* Wk2 = (const float*)d_in[13]; const float* bk2 = (const float*)d_in[14];
    const float* Wv2 = (const float*)d_in[15]; const float* bv2 = (const float*)d_in[16];
    const float* Ws2 = (const float*)d_in[17]; const float* bs2 = (const float*)d_in[18];
    float* out = (float*)d_out;

    float *xtp, *qp, *skp; __half2 *khp, *vhp;
    cudaGetSymbolAddress((void**)&xtp, g_xt);
    cudaGetSymbolAddress((void**)&qp,  g_q);
    cudaGetSymbolAddress((void**)&khp, g_kh);
    cudaGetSymbolAddress((void**)&vhp, g_vh);
    cudaGetSymbolAddress((void**)&skp, g_skip);

    const int smemBytes = (TILE_R + DD) * LDS_PAD * (int)sizeof(float);  // ~99 KB
    cudaFuncSetAttribute(gemm_all_kernel,
                         cudaFuncAttributeMaxDynamicSharedMemorySize, smemBytes);

    int edgeBlocks = (EE + 255) / 256;
    int nodeBlocks = (NN * 32 + 255) / 256;
    int zeroBlocks = (NN + 1023) / 1024;

    cudaStream_t s2 = g_ss.s2;

    // fork: CSR build runs on s2, overlapping prep_w + gemm1 on the main stream
    cudaEventRecord(g_ss.ev_fork, 0);
    cudaStreamWaitEvent(s2, g_ss.ev_fork, 0);
    zero_deg_kernel<<<zeroBlocks, 1024, 0, s2>>>();
    hist_kernel<<<edgeBlocks, 256, 0, s2>>>(ei);
    csr_bsum_kernel<<<NB, 1024, 0, s2>>>();
    csr_scanb_kernel<<<1, 128, 0, s2>>>();
    csr_offsets_kernel<<<NB, 1024, 0, s2>>>();
    csr_scatter_kernel<<<edgeBlocks, 256, 0, s2>>>(ei);
    cudaEventRecord(g_ss.ev_join, s2);

    // main stream: weights + layer-1 GEMM
    prep_w_kernel<<<dim3(4, 4, 8), dim3(32, 8)>>>(Wq1, Wk1, Wv1, Ws1,
                                                  Wq2, Wk2, Wv2, Ws2);
    gemm_all_kernel<<<GEMM_GRID, 256, smemBytes>>>(0, x,
        bq1, bk1, bv1, bs1, qp, khp, vhp, skp);

    // join: attn needs CSR + gemm1
    cudaStreamWaitEvent(0, g_ss.ev_join, 0);
    node_attn_kernel<<<nodeBlocks, 256>>>(qp, khp, vhp, skp, nullptr, a, xtp, 1);

    gemm_all_kernel<<<GEMM_GRID, 256, smemBytes>>>(4, xtp,
        bq2, bk2, bv2, bs2, qp, khp, vhp, skp);
    node_attn_kernel<<<nodeBlocks, 256>>>(qp, khp, vhp, skp, x, a, out, 0);
}

// round 10
// speedup vs baseline: 1.0902x; 1.0902x over previous
#include <cuda_runtime.h>
#include <cuda_fp16.h>
#include <cstdint>
#include <cstddef>

#define NN 100000
#define EE 1000000
#define DD 128
#define HH 8
#define SCALE_ATT 0.25f   // 1/sqrt(16)
#define LDS_PAD 132       // smem row stride (floats)
#define NB 98             // scan blocks of 1024 covering NN (+1)
#define TILE_R 64
#define NTILES ((NN + TILE_R - 1) / TILE_R)   // 1563
#define GEMM_GRID 296

// ---------------- scratch (static device globals) --------------------------
__device__ float   g_xt[NN * DD];      // layer-2 GEMM input (tf32, from attn1)
__device__ float   g_wt[8 * DD * DD];  // tf32-rounded, transposed weights Wt[c][k]
__device__ float   g_q[NN * DD];
__device__ __half2 g_kh[NN * DD / 2];  // fp16 k
__device__ __half2 g_vh[NN * DD / 2];  // fp16 v
__device__ float   g_skip[NN * DD];
__device__ int     g_deg[NN];
__device__ int     g_roff[NN + 1];
__device__ int     g_mut[NN];
__device__ int     g_csr[EE];
__device__ int     g_bsum[NB];
__device__ int     g_bpre[NB];

// ---- side stream + events, created at load time (before harness baseline) --
namespace {
struct SideStream {
    cudaStream_t s2 = nullptr;
    cudaEvent_t ev_fork = nullptr, ev_join = nullptr;
    SideStream() {
        cudaStreamCreateWithFlags(&s2, cudaStreamNonBlocking);
        cudaEventCreateWithFlags(&ev_fork, cudaEventDisableTiming);
        cudaEventCreateWithFlags(&ev_join, cudaEventDisableTiming);
    }
};
SideStream g_ss;
}

__device__ __forceinline__ float tf32r(float x) {
    uint32_t u;
    asm("cvt.rna.tf32.f32 %0, %1;" : "=r"(u) : "f"(x));
    return __uint_as_float(u);
}

#define CP_ASYNC16(dst_u32, src_ptr) \
    asm volatile("cp.async.cg.shared.global [%0], [%1], 16;" \
                 :: "r"(dst_u32), "l"(src_ptr))
#define CP_ASYNC_COMMIT() asm volatile("cp.async.commit_group;")
#define CP_ASYNC_WAIT0()  asm volatile("cp.async.wait_group 0;")

// ================= CSR build =================
__global__ void zero_deg_kernel() {
    int i = blockIdx.x * blockDim.x + threadIdx.x;
    if (i < NN) g_deg[i] = 0;
}

__global__ void hist_kernel(const int* __restrict__ ei) {
    int e = blockIdx.x * blockDim.x + threadIdx.x;
    if (e < EE) atomicAdd(&g_deg[ei[EE + e]], 1);
}

__global__ void csr_bsum_kernel() {
    __shared__ int sm[1024];
    int tid = threadIdx.x;
    int idx = blockIdx.x * 1024 + tid;
    sm[tid] = (idx < NN) ? g_deg[idx] : 0;
    __syncthreads();
    for (int s = 512; s > 0; s >>= 1) {
        if (tid < s) sm[tid] += sm[tid + s];
        __syncthreads();
    }
    if (tid == 0) g_bsum[blockIdx.x] = sm[0];
}

__global__ void csr_scanb_kernel() {
    __shared__ int sm[128];
    int tid = threadIdx.x;
    int v = (tid < NB) ? g_bsum[tid] : 0;
    sm[tid] = v;
    __syncthreads();
    for (int off = 1; off < 128; off <<= 1) {
        int t = (tid >= off) ? sm[tid - off] : 0;
        __syncthreads();
        sm[tid] += t;
        __syncthreads();
    }
    if (tid < NB) g_bpre[tid] = sm[tid] - v;   // exclusive
}

__global__ void csr_offsets_kernel() {
    __shared__ int sm[1024];
    int tid = threadIdx.x;
    int idx = blockIdx.x * 1024 + tid;
    int v = (idx < NN) ? g_deg[idx] : 0;
    sm[tid] = v;
    __syncthreads();
    for (int off = 1; off < 1024; off <<= 1) {
        int t = (tid >= off) ? sm[tid - off] : 0;
        __syncthreads();
        sm[tid] += t;
        __syncthreads();
    }
    int excl = sm[tid] - v + g_bpre[blockIdx.x];
    if (idx < NN) { g_roff[idx] = excl; g_mut[idx] = excl; }
    if (idx == NN) g_roff[NN] = excl;          // == EE
}

__global__ void csr_scatter_kernel(const int* __restrict__ ei) {
    int e = blockIdx.x * blockDim.x + threadIdx.x;
    if (e >= EE) return;
    int s = ei[e], d = ei[EE + e];
    int pos = atomicAdd(&g_mut[d], 1);
    g_csr[pos] = s;
}

// ================= weight prep =================
__global__ void prep_w_kernel(
    const float* __restrict__ W0, const float* __restrict__ W1,
    const float* __restrict__ W2, const float* __restrict__ W3,
    const float* __restrict__ W4, const float* __restrict__ W5,
    const float* __restrict__ W6, const float* __restrict__ W7)
{
    const float* Ws[8] = {W0, W1, W2, W3, W4, W5, W6, W7};
    int m = blockIdx.z;
    const float* W = Ws[m];
    __shared__ float t[32][33];
    int k0 = blockIdx.x * 32, c0 = blockIdx.y * 32;
    int tx = threadIdx.x, ty = threadIdx.y;
#pragma unroll
    for (int i = 0; i < 4; i++)
        t[ty + 8 * i][tx] = tf32r(W[(k0 + ty + 8 * i) * DD + c0 + tx]);
    __syncthreads();
#pragma unroll
    for (int i = 0; i < 4; i++)
        g_wt[m * DD * DD + (c0 + ty + 8 * i) * DD + k0 + tx] = t[tx][ty + 8 * i];
}

// ================= persistent merged 4-matrix tf32 GEMM =================
__global__ __launch_bounds__(256, 2) void gemm_all_kernel(
    int wofs, const float* __restrict__ X,
    const float* __restrict__ B0, const float* __restrict__ B1,
    const float* __restrict__ B2, const float* __restrict__ B3,
    float* Oq, __half2* Ok, __half2* Ov, float* Osk)
{
    extern __shared__ float smem[];
    float* Xs = smem;                       // [64][LDS_PAD]
    float* Ws = smem + TILE_R * LDS_PAD;    // [128][LDS_PAD]  W[c][k]

    const float* Bs[4] = {B0, B1, B2, B3};

    int tid = threadIdx.x;
    int warp = tid >> 5, lane = tid & 31;
    int rbase = (warp >> 2) * 32;           // {0,32}
    int cbase = (warp & 3) * 32;            // {0,32,64,96}
    int lr = lane >> 2, lk = lane & 3;

    uint32_t ws_b = (uint32_t)__cvta_generic_to_shared(Ws);

#pragma unroll 1
    for (int m = 0; m < 4; m++) {
        const float* Wt = g_wt + (size_t)(wofs + m) * DD * DD;
#pragma unroll
        for (int it = 0; it < 16; it++) {
            int i = tid + it * 256;
            int r = i >> 5, c4 = (i & 31) * 4;
            CP_ASYNC16(ws_b + (r * LDS_PAD + c4) * 4, Wt + (size_t)r * DD + c4);
        }
        CP_ASYNC_COMMIT();

        const float* B = Bs[m];
        float bb[4][2];
#pragma unroll
        for (int nt = 0; nt < 4; nt++) {
            int col = cbase + nt * 8 + 2 * lk;
            bb[nt][0] = B[col]; bb[nt][1] = B[col + 1];
        }

        CP_ASYNC_WAIT0();

        for (int t = blockIdx.x; t < NTILES; t += GEMM_GRID) {
            int row0 = t * TILE_R;
            __syncthreads();   // prior compute done (Xs safe) + W visible
#pragma unroll
            for (int it = 0; it < 8; it++) {
                int i = tid + it * 256;
                int r = i >> 5, c4 = (i & 31) * 4;
                int gr = row0 + r; if (gr >= NN) gr = NN - 1;
                float4 xv = *(const float4*)(X + (size_t)gr * DD + c4);
                float* p = Xs + r * LDS_PAD + c4;
                p[0] = tf32r(xv.x); p[1] = tf32r(xv.y);
                p[2] = tf32r(xv.z); p[3] = tf32r(xv.w);
            }
            __syncthreads();

            float acc[2][4][4];
#pragma unroll
            for (int nt = 0; nt < 4; nt++)
#pragma unroll
                for (int mt = 0; mt < 2; mt++) {
                    acc[mt][nt][0] = bb[nt][0]; acc[mt][nt][1] = bb[nt][1];
                    acc[mt][nt][2] = bb[nt][0]; acc[mt][nt][3] = bb[nt][1];
                }

#pragma unroll
            for (int ks = 0; ks < 16; ks++) {
                int k0 = ks * 8;
                uint32_t a[2][4];
#pragma unroll
                for (int mt = 0; mt < 2; mt++) {
                    const float* base = Xs + (rbase + mt * 16 + lr) * LDS_PAD + k0 + lk;
                    a[mt][0] = __float_as_uint(base[0]);
                    a[mt][1] = __float_as_uint(base[8 * LDS_PAD]);
                    a[mt][2] = __float_as_uint(base[4]);
                    a[mt][3] = __float_as_uint(base[8 * LDS_PAD + 4]);
                }
#pragma unroll
                for (int nt = 0; nt < 4; nt++) {
                    const float* bbase = Ws + (cbase + nt * 8 + lr) * LDS_PAD + k0 + lk;
                    uint32_t b0 = __float_as_uint(bbase[0]);
                    uint32_t b1 = __float_as_uint(bbase[4]);
#pragma unroll
                    for (int mt = 0; mt < 2; mt++) {
                        asm volatile(
                            "mma.sync.aligned.m16n8k8.row.col.f32.tf32.tf32.f32 "
                            "{%0,%1,%2,%3}, {%4,%5,%6,%7}, {%8,%9}, {%0,%1,%2,%3};"
                            : "+f"(acc[mt][nt][0]), "+f"(acc[mt][nt][1]),
                              "+f"(acc[mt][nt][2]), "+f"(acc[mt][nt][3])
                            : "r"(a[mt][0]), "r"(a[mt][1]), "r"(a[mt][2]), "r"(a[mt][3]),
                              "r"(b0), "r"(b1));
                    }
                }
            }

            if (m == 0 || m == 3) {
                float* O = (m == 0) ? Oq : Osk;
#pragma unroll
                for (int mt = 0; mt < 2; mt++) {
                    int gr0 = row0 + rbase + mt * 16 + lr;
                    int gr1 = gr0 + 8;
#pragma unroll
                    for (int nt = 0; nt < 4; nt++) {
                        int col = cbase + nt * 8 + 2 * lk;
                        if (gr0 < NN)
                            *(float2*)(O + (size_t)gr0 * DD + col) =
                                make_float2(acc[mt][nt][0], acc[mt][nt][1]);
                        if (gr1 < NN)
                            *(float2*)(O + (size_t)gr1 * DD + col) =
                                make_float2(acc[mt][nt][2], acc[mt][nt][3]);
                    }
                }
            } else {
                __half2* O = (m == 1) ? Ok : Ov;
#pragma unroll
                for (int mt = 0; mt < 2; mt++) {
                    int gr0 = row0 + rbase + mt * 16 + lr;
                    int gr1 = gr0 + 8;
#pragma unroll
                    for (int nt = 0; nt < 4; nt++) {
                        int col = cbase + nt * 8 + 2 * lk;
                        if (gr0 < NN)
                            O[(size_t)gr0 * (DD / 2) + (col >> 1)] =
                                __floats2half2_rn(acc[mt][nt][0], acc[mt][nt][1]);
                        if (gr1 < NN)
                            O[(size_t)gr1 * (DD / 2) + (col >> 1)] =
                                __floats2half2_rn(acc[mt][nt][2], acc[mt][nt][3]);
                    }
                }
            }
        }
        __syncthreads();   // all reads of Ws done before next m overwrites
    }
}

// ================= warp-per-node attention aggregation (R8 version) ========
__global__ __launch_bounds__(256) void node_attn_kernel(
    const float* __restrict__ q, const __half2* __restrict__ kh,
    const __half2* __restrict__ vh, const float* __restrict__ skip,
    const float* __restrict__ resid, const float* __restrict__ a_ptr,
    float* __restrict__ out, int do_tf32)
{
    int n = (blockIdx.x * blockDim.x + threadIdx.x) >> 5;
    if (n >= NN) return;
    int lane = threadIdx.x & 31;

    float4 qv = ((const float4*)(q + (size_t)n * DD))[lane];
    int j0 = g_roff[n], j1 = g_roff[n + 1];

    float4 acc = make_float4(0.f, 0.f, 0.f, 0.f);
    float ws = 0.f;

#pragma unroll 4
    for (int j = j0; j < j1; j++) {
        int s = g_csr[j];
        uint2 kk = ((const uint2*)(kh + (size_t)s * (DD / 2)))[lane];
        float2 k0 = __half22float2(*(const __half2*)&kk.x);
        float2 k1 = __half22float2(*(const __half2*)&kk.y);
        float p = qv.x * k0.x + qv.y * k0.y + qv.z * k1.x + qv.w * k1.y;
        p += __shfl_xor_sync(0xFFFFFFFFu, p, 1);
        p += __shfl_xor_sync(0xFFFFFFFFu, p, 2);
        float w = __expf(p * SCALE_ATT);
        ws += w;
        uint2 vv = ((const uint2*)(vh + (size_t)s * (DD / 2)))[lane];
        float2 v0 = __half22float2(*(const __half2*)&vv.x);
        float2 v1 = __half22float2(*(const __half2*)&vv.y);
        acc.x += w * v0.x; acc.y += w * v0.y;
        acc.z += w * v1.x; acc.w += w * v1.y;
    }

    float inv = (ws > 0.f) ? 1.f / ws : 0.f;
    float4 sk = ((const float4*)(skip + (size_t)n * DD))[lane];
    float4 y;
    y.x = acc.x * inv + sk.x;
    y.y = acc.y * inv + sk.y;
    y.z = acc.z * inv + sk.z;
    y.w = acc.w * inv + sk.w;
    if (resid) {
        float4 rv = ((const float4*)(resid + (size_t)n * DD))[lane];
        y.x += rv.x; y.y += rv.y; y.z += rv.z; y.w += rv.w;
    }
    float a = *a_ptr;
    y.x = (y.x >= 0.f) ? y.x : a * y.x;
    y.y = (y.y >= 0.f) ? y.y : a * y.y;
    y.z = (y.z >= 0.f) ? y.z : a * y.z;
    y.w = (y.w >= 0.f) ? y.w : a * y.w;
    if (do_tf32) {
        y.x = tf32r(y.x); y.y = tf32r(y.y);
        y.z = tf32r(y.z); y.w = tf32r(y.w);
    }
    ((float4*)(out + (size_t)n * DD))[lane] = y;
}

// ---------------- host launch ----------------------------------------------
extern "C" void kernel_launch(void* const* d_in, const int* in_sizes, int n_in,
                              void* d_out, int out_size)
{
    (void)in_sizes; (void)n_in; (void)out_size;
    const float* x   = (const float*)d_in[0];
    const int*   ei  = (const int*)d_in[1];
    const float* a   = (const float*)d_in[2];
    const float* Wq1 = (const float*)d_in[3];  const float* bq1 = (const float*)d_in[4];
    const float* Wk1 = (const float*)d_in[5];  const float* bk1 = (const float*)d_in[6];
    const float* Wv1 = (const float*)d_in[7];  const float* bv1 = (const float*)d_in[8];
    const float* Ws1 = (const float*)d_in[9];  const float* bs1 = (const float*)d_in[10];
    const float* Wq2 = (const float*)d_in[11]; const float* bq2 = (const float*)d_in[12];
    const float* Wk2 = (const float*)d_in[13]; const float* bk2 = (const float*)d_in[14];
    const float* Wv2 = (const float*)d_in[15]; const float* bv2 = (const float*)d_in[16];
    const float* Ws2 = (const float*)d_in[17]; const float* bs2 = (const float*)d_in[18];
    float* out = (float*)d_out;

    float *xtp, *qp, *skp; __half2 *khp, *vhp;
    cudaGetSymbolAddress((void**)&xtp, g_xt);
    cudaGetSymbolAddress((void**)&qp,  g_q);
    cudaGetSymbolAddress((void**)&khp, g_kh);
    cudaGetSymbolAddress((void**)&vhp, g_vh);
    cudaGetSymbolAddress((void**)&skp, g_skip);

    const int smemBytes = (TILE_R + DD) * LDS_PAD * (int)sizeof(float);  // ~99 KB
    cudaFuncSetAttribute(gemm_all_kernel,
                         cudaFuncAttributeMaxDynamicSharedMemorySize, smemBytes);

    int edgeBlocks = (EE + 255) / 256;
    int nodeBlocks = (NN * 32 + 255) / 256;
    int zeroBlocks = (NN + 1023) / 1024;

    cudaStream_t s2 = g_ss.s2;

    // fork: CSR build on s2, overlapping prep_w + gemm1 on the main stream
    cudaEventRecord(g_ss.ev_fork, 0);
    cudaStreamWaitEvent(s2, g_ss.ev_fork, 0);
    zero_deg_kernel<<<zeroBlocks, 1024, 0, s2>>>();
    hist_kernel<<<edgeBlocks, 256, 0, s2>>>(ei);
    csr_bsum_kernel<<<NB, 1024, 0, s2>>>();
    csr_scanb_kernel<<<1, 128, 0, s2>>>();
    csr_offsets_kernel<<<NB, 1024, 0, s2>>>();
    csr_scatter_kernel<<<edgeBlocks, 256, 0, s2>>>(ei);
    cudaEventRecord(g_ss.ev_join, s2);

    // main stream: weights + layer-1 GEMM
    prep_w_kernel<<<dim3(4, 4, 8), dim3(32, 8)>>>(Wq1, Wk1, Wv1, Ws1,
                                                  Wq2, Wk2, Wv2, Ws2);
    gemm_all_kernel<<<GEMM_GRID, 256, smemBytes>>>(0, x,
        bq1, bk1, bv1, bs1, qp, khp, vhp, skp);

    // join: attn needs CSR + gemm1
    cudaStreamWaitEvent(0, g_ss.ev_join, 0);
    node_attn_kernel<<<nodeBlocks, 256>>>(qp, khp, vhp, skp, nullptr, a, xtp, 1);

    gemm_all_kernel<<<GEMM_GRID, 256, smemBytes>>>(4, xtp,
        bq2, bk2, bv2, bs2, qp, khp, vhp, skp);
    node_attn_kernel<<<nodeBlocks, 256>>>(qp, khp, vhp, skp, x, a, out, 0);
}

// round 11
// speedup vs baseline: 1.3184x; 1.2093x over previous
#include <cuda_runtime.h>
#include <cuda_fp16.h>
#include <cstdint>
#include <cstddef>

#define NN 100000
#define EE 1000000
#define DD 128
#define HH 8
#define SCALE_ATT 0.25f   // 1/sqrt(16)
#define PADH 136          // smem row stride in halves (272 B): conflict-free frags
#define NB 98             // scan blocks of 1024 covering NN (+1)
#define TILE_R 64
#define NTILES ((NN + TILE_R - 1) / TILE_R)   // 1563
#define GEMM_GRID 444     // 3 CTAs/SM

// ---------------- scratch (static device globals) --------------------------
__device__ __half  g_xt[NN * DD];      // layer-2 GEMM input (fp16, from attn1)
__device__ __half  g_wt[8 * DD * DD];  // fp16, transposed weights Wt[c][k]
__device__ float   g_q[NN * DD];
__device__ __half2 g_kh[NN * DD / 2];  // fp16 k
__device__ __half2 g_vh[NN * DD / 2];  // fp16 v
__device__ float   g_skip[NN * DD];
__device__ int     g_deg[NN];
__device__ int     g_roff[NN + 1];
__device__ int     g_mut[NN];
__device__ int     g_csr[EE];
__device__ int     g_bsum[NB];
__device__ int     g_bpre[NB];

// ---- side stream + events, created at load time (before harness baseline) --
namespace {
struct SideStream {
    cudaStream_t s2 = nullptr;
    cudaEvent_t ev_fork = nullptr, ev_join = nullptr;
    SideStream() {
        cudaStreamCreateWithFlags(&s2, cudaStreamNonBlocking);
        cudaEventCreateWithFlags(&ev_fork, cudaEventDisableTiming);
        cudaEventCreateWithFlags(&ev_join, cudaEventDisableTiming);
    }
};
SideStream g_ss;
}

#define CP_ASYNC16(dst_u32, src_ptr) \
    asm volatile("cp.async.cg.shared.global [%0], [%1], 16;" \
                 :: "r"(dst_u32), "l"(src_ptr))
#define CP_ASYNC_COMMIT() asm volatile("cp.async.commit_group;")
#define CP_ASYNC_WAIT0()  asm volatile("cp.async.wait_group 0;")

// ================= CSR build =================
__global__ void zero_deg_kernel() {
    int i = blockIdx.x * blockDim.x + threadIdx.x;
    if (i < NN) g_deg[i] = 0;
}

__global__ void hist_kernel(const int* __restrict__ ei) {
    int e = blockIdx.x * blockDim.x + threadIdx.x;
    if (e < EE) atomicAdd(&g_deg[ei[EE + e]], 1);
}

__global__ void csr_bsum_kernel() {
    __shared__ int sm[1024];
    int tid = threadIdx.x;
    int idx = blockIdx.x * 1024 + tid;
    sm[tid] = (idx < NN) ? g_deg[idx] : 0;
    __syncthreads();
    for (int s = 512; s > 0; s >>= 1) {
        if (tid < s) sm[tid] += sm[tid + s];
        __syncthreads();
    }
    if (tid == 0) g_bsum[blockIdx.x] = sm[0];
}

__global__ void csr_scanb_kernel() {
    __shared__ int sm[128];
    int tid = threadIdx.x;
    int v = (tid < NB) ? g_bsum[tid] : 0;
    sm[tid] = v;
    __syncthreads();
    for (int off = 1; off < 128; off <<= 1) {
        int t = (tid >= off) ? sm[tid - off] : 0;
        __syncthreads();
        sm[tid] += t;
        __syncthreads();
    }
    if (tid < NB) g_bpre[tid] = sm[tid] - v;   // exclusive
}

__global__ void csr_offsets_kernel() {
    __shared__ int sm[1024];
    int tid = threadIdx.x;
    int idx = blockIdx.x * 1024 + tid;
    int v = (idx < NN) ? g_deg[idx] : 0;
    sm[tid] = v;
    __syncthreads();
    for (int off = 1; off < 1024; off <<= 1) {
        int t = (tid >= off) ? sm[tid - off] : 0;
        __syncthreads();
        sm[tid] += t;
        __syncthreads();
    }
    int excl = sm[tid] - v + g_bpre[blockIdx.x];
    if (idx < NN) { g_roff[idx] = excl; g_mut[idx] = excl; }
    if (idx == NN) g_roff[NN] = excl;          // == EE
}

__global__ void csr_scatter_kernel(const int* __restrict__ ei) {
    int e = blockIdx.x * blockDim.x + threadIdx.x;
    if (e >= EE) return;
    int s = ei[e], d = ei[EE + e];
    int pos = atomicAdd(&g_mut[d], 1);
    g_csr[pos] = s;
}

// ================= weight prep: transpose + fp16 =================
__global__ void prep_w_kernel(
    const float* __restrict__ W0, const float* __restrict__ W1,
    const float* __restrict__ W2, const float* __restrict__ W3,
    const float* __restrict__ W4, const float* __restrict__ W5,
    const float* __restrict__ W6, const float* __restrict__ W7)
{
    const float* Ws[8] = {W0, W1, W2, W3, W4, W5, W6, W7};
    int m = blockIdx.z;
    const float* W = Ws[m];
    __shared__ float t[32][33];
    int k0 = blockIdx.x * 32, c0 = blockIdx.y * 32;
    int tx = threadIdx.x, ty = threadIdx.y;
#pragma unroll
    for (int i = 0; i < 4; i++)
        t[ty + 8 * i][tx] = W[(k0 + ty + 8 * i) * DD + c0 + tx];
    __syncthreads();
#pragma unroll
    for (int i = 0; i < 4; i++)
        g_wt[m * DD * DD + (c0 + ty + 8 * i) * DD + k0 + tx] =
            __float2half_rn(t[tx][ty + 8 * i]);
}

// ================= persistent merged 4-matrix fp16 GEMM =================
// 444 blocks (3 CTA/SM), 256 threads. m (weight matrix) outer loop; 64-row
// X tiles inner. mma.m16n8k16.f32.f16.f16.f32, 8 k-steps.
__global__ __launch_bounds__(256, 3) void gemm_all_kernel(
    int wofs, const float* __restrict__ Xf, const __half* __restrict__ Xh,
    const float* __restrict__ B0, const float* __restrict__ B1,
    const float* __restrict__ B2, const float* __restrict__ B3,
    float* Oq, __half2* Ok, __half2* Ov, float* Osk)
{
    extern __shared__ __half smem[];
    __half* Xs = smem;                       // [64][PADH]
    __half* Ws = smem + TILE_R * PADH;       // [128][PADH]  W[c][k]

    const float* Bs[4] = {B0, B1, B2, B3};

    int tid = threadIdx.x;
    int warp = tid >> 5, lane = tid & 31;
    int rbase = (warp >> 2) * 32;           // {0,32}
    int cbase = (warp & 3) * 32;            // {0,32,64,96}
    int lr = lane >> 2, lk = lane & 3;

    uint32_t ws_b = (uint32_t)__cvta_generic_to_shared(Ws);

#pragma unroll 1
    for (int m = 0; m < 4; m++) {
        // load W_m (128 c-rows x 128 k halves) via cp.async, 8 halves/op
        const __half* Wt = g_wt + (size_t)(wofs + m) * DD * DD;
#pragma unroll
        for (int it = 0; it < 8; it++) {
            int i = tid + it * 256;          // 0..2047
            int r = i >> 4, g = i & 15;      // 16 groups of 8 halves per row
            CP_ASYNC16(ws_b + (r * PADH + g * 8) * 2, Wt + (size_t)r * DD + g * 8);
        }
        CP_ASYNC_COMMIT();

        const float* B = Bs[m];
        float bb[4][2];
#pragma unroll
        for (int nt = 0; nt < 4; nt++) {
            int col = cbase + nt * 8 + 2 * lk;
            bb[nt][0] = B[col]; bb[nt][1] = B[col + 1];
        }

        CP_ASYNC_WAIT0();

        for (int t = blockIdx.x; t < NTILES; t += GEMM_GRID) {
            int row0 = t * TILE_R;
            __syncthreads();   // prior compute done (Xs safe) + W visible
            // load X tile (64x128), converting to fp16 if source is fp32
#pragma unroll
            for (int it = 0; it < 8; it++) {
                int i = tid + it * 256;      // 0..2047
                int r = i >> 5, c4 = (i & 31) * 4;
                int gr = row0 + r; if (gr >= NN) gr = NN - 1;
                uint2 hv;
                if (Xf) {
                    float4 xv = *(const float4*)(Xf + (size_t)gr * DD + c4);
                    __half2 h0 = __floats2half2_rn(xv.x, xv.y);
                    __half2 h1 = __floats2half2_rn(xv.z, xv.w);
                    hv.x = *(uint32_t*)&h0; hv.y = *(uint32_t*)&h1;
                } else {
                    hv = *(const uint2*)(Xh + (size_t)gr * DD + c4);
                }
                *(uint2*)(Xs + r * PADH + c4) = hv;
            }
            __syncthreads();

            float acc[2][4][4];
#pragma unroll
            for (int nt = 0; nt < 4; nt++)
#pragma unroll
                for (int mt = 0; mt < 2; mt++) {
                    acc[mt][nt][0] = bb[nt][0]; acc[mt][nt][1] = bb[nt][1];
                    acc[mt][nt][2] = bb[nt][0]; acc[mt][nt][3] = bb[nt][1];
                }

#pragma unroll
            for (int ks = 0; ks < 8; ks++) {
                int k0 = ks * 16;
                uint32_t a[2][4];
#pragma unroll
                for (int mt = 0; mt < 2; mt++) {
                    const __half* base = Xs + (rbase + mt * 16 + lr) * PADH + k0 + 2 * lk;
                    a[mt][0] = *(const uint32_t*)(base);
                    a[mt][1] = *(const uint32_t*)(base + 8 * PADH);
                    a[mt][2] = *(const uint32_t*)(base + 8);
                    a[mt][3] = *(const uint32_t*)(base + 8 * PADH + 8);
                }
#pragma unroll
                for (int nt = 0; nt < 4; nt++) {
                    const __half* wb = Ws + (cbase + nt * 8 + lr) * PADH + k0 + 2 * lk;
                    uint32_t b0 = *(const uint32_t*)(wb);
                    uint32_t b1 = *(const uint32_t*)(wb + 8);
#pragma unroll
                    for (int mt = 0; mt < 2; mt++) {
                        asm volatile(
                            "mma.sync.aligned.m16n8k16.row.col.f32.f16.f16.f32 "
                            "{%0,%1,%2,%3}, {%4,%5,%6,%7}, {%8,%9}, {%0,%1,%2,%3};"
                            : "+f"(acc[mt][nt][0]), "+f"(acc[mt][nt][1]),
                              "+f"(acc[mt][nt][2]), "+f"(acc[mt][nt][3])
                            : "r"(a[mt][0]), "r"(a[mt][1]), "r"(a[mt][2]), "r"(a[mt][3]),
                              "r"(b0), "r"(b1));
                    }
                }
            }

            if (m == 0 || m == 3) {
                float* O = (m == 0) ? Oq : Osk;
#pragma unroll
                for (int mt = 0; mt < 2; mt++) {
                    int gr0 = row0 + rbase + mt * 16 + lr;
                    int gr1 = gr0 + 8;
#pragma unroll
                    for (int nt = 0; nt < 4; nt++) {
                        int col = cbase + nt * 8 + 2 * lk;
                        if (gr0 < NN)
                            *(float2*)(O + (size_t)gr0 * DD + col) =
                                make_float2(acc[mt][nt][0], acc[mt][nt][1]);
                        if (gr1 < NN)
                            *(float2*)(O + (size_t)gr1 * DD + col) =
                                make_float2(acc[mt][nt][2], acc[mt][nt][3]);
                    }
                }
            } else {
                __half2* O = (m == 1) ? Ok : Ov;
#pragma unroll
                for (int mt = 0; mt < 2; mt++) {
                    int gr0 = row0 + rbase + mt * 16 + lr;
                    int gr1 = gr0 + 8;
#pragma unroll
                    for (int nt = 0; nt < 4; nt++) {
                        int col = cbase + nt * 8 + 2 * lk;
                        if (gr0 < NN)
                            O[(size_t)gr0 * (DD / 2) + (col >> 1)] =
                                __floats2half2_rn(acc[mt][nt][0], acc[mt][nt][1]);
                        if (gr1 < NN)
                            O[(size_t)gr1 * (DD / 2) + (col >> 1)] =
                                __floats2half2_rn(acc[mt][nt][2], acc[mt][nt][3]);
                    }
                }
            }
        }
        __syncthreads();   // all reads of Ws done before next m overwrites
    }
}

// ================= warp-per-node attention aggregation =================
// outf != nullptr -> final fp32 output; else writes fp16 into outh (layer-2 xt)
__global__ __launch_bounds__(256) void node_attn_kernel(
    const float* __restrict__ q, const __half2* __restrict__ kh,
    const __half2* __restrict__ vh, const float* __restrict__ skip,
    const float* __restrict__ resid, const float* __restrict__ a_ptr,
    float* __restrict__ outf, __half* __restrict__ outh)
{
    int n = (blockIdx.x * blockDim.x + threadIdx.x) >> 5;
    if (n >= NN) return;
    int lane = threadIdx.x & 31;

    float4 qv = ((const float4*)(q + (size_t)n * DD))[lane];
    int j0 = g_roff[n], j1 = g_roff[n + 1];

    float4 acc = make_float4(0.f, 0.f, 0.f, 0.f);
    float ws = 0.f;

#pragma unroll 4
    for (int j = j0; j < j1; j++) {
        int s = g_csr[j];
        uint2 kk = ((const uint2*)(kh + (size_t)s * (DD / 2)))[lane];
        float2 k0 = __half22float2(*(const __half2*)&kk.x);
        float2 k1 = __half22float2(*(const __half2*)&kk.y);
        float p = qv.x * k0.x + qv.y * k0.y + qv.z * k1.x + qv.w * k1.y;
        p += __shfl_xor_sync(0xFFFFFFFFu, p, 1);
        p += __shfl_xor_sync(0xFFFFFFFFu, p, 2);
        float w = __expf(p * SCALE_ATT);
        ws += w;
        uint2 vv = ((const uint2*)(vh + (size_t)s * (DD / 2)))[lane];
        float2 v0 = __half22float2(*(const __half2*)&vv.x);
        float2 v1 = __half22float2(*(const __half2*)&vv.y);
        acc.x += w * v0.x; acc.y += w * v0.y;
        acc.z += w * v1.x; acc.w += w * v1.y;
    }

    float inv = (ws > 0.f) ? 1.f / ws : 0.f;
    float4 sk = ((const float4*)(skip + (size_t)n * DD))[lane];
    float4 y;
    y.x = acc.x * inv + sk.x;
    y.y = acc.y * inv + sk.y;
    y.z = acc.z * inv + sk.z;
    y.w = acc.w * inv + sk.w;
    if (resid) {
        float4 rv = ((const float4*)(resid + (size_t)n * DD))[lane];
        y.x += rv.x; y.y += rv.y; y.z += rv.z; y.w += rv.w;
    }
    float a = *a_ptr;
    y.x = (y.x >= 0.f) ? y.x : a * y.x;
    y.y = (y.y >= 0.f) ? y.y : a * y.y;
    y.z = (y.z >= 0.f) ? y.z : a * y.z;
    y.w = (y.w >= 0.f) ? y.w : a * y.w;
    if (outf) {
        ((float4*)(outf + (size_t)n * DD))[lane] = y;
    } else {
        __half2 h0 = __floats2half2_rn(y.x, y.y);
        __half2 h1 = __floats2half2_rn(y.z, y.w);
        uint2 hv; hv.x = *(uint32_t*)&h0; hv.y = *(uint32_t*)&h1;
        ((uint2*)(outh + (size_t)n * DD))[lane] = hv;
    }
}

// ---------------- host launch ----------------------------------------------
extern "C" void kernel_launch(void* const* d_in, const int* in_sizes, int n_in,
                              void* d_out, int out_size)
{
    (void)in_sizes; (void)n_in; (void)out_size;
    const float* x   = (const float*)d_in[0];
    const int*   ei  = (const int*)d_in[1];
    const float* a   = (const float*)d_in[2];
    const float* Wq1 = (const float*)d_in[3];  const float* bq1 = (const float*)d_in[4];
    const float* Wk1 = (const float*)d_in[5];  const float* bk1 = (const float*)d_in[6];
    const float* Wv1 = (const float*)d_in[7];  const float* bv1 = (const float*)d_in[8];
    const float* Ws1 = (const float*)d_in[9];  const float* bs1 = (const float*)d_in[10];
    const float* Wq2 = (const float*)d_in[11]; const float* bq2 = (const float*)d_in[12];
    const float* Wk2 = (const float*)d_in[13]; const float* bk2 = (const float*)d_in[14];
    const float* Wv2 = (const float*)d_in[15]; const float* bv2 = (const float*)d_in[16];
    const float* Ws2 = (const float*)d_in[17]; const float* bs2 = (const float*)d_in[18];
    float* out = (float*)d_out;

    float *qp, *skp; __half *xtp; __half2 *khp, *vhp;
    cudaGetSymbolAddress((void**)&xtp, g_xt);
    cudaGetSymbolAddress((void**)&qp,  g_q);
    cudaGetSymbolAddress((void**)&khp, g_kh);
    cudaGetSymbolAddress((void**)&vhp, g_vh);
    cudaGetSymbolAddress((void**)&skp, g_skip);

    const int smemBytes = (TILE_R + DD) * PADH * (int)sizeof(__half);  // ~51 KB
    cudaFuncSetAttribute(gemm_all_kernel,
                         cudaFuncAttributeMaxDynamicSharedMemorySize, smemBytes);

    int edgeBlocks = (EE + 255) / 256;
    int nodeBlocks = (NN * 32 + 255) / 256;
    int zeroBlocks = (NN + 1023) / 1024;

    cudaStream_t s2 = g_ss.s2;

    // fork: CSR build on s2, overlapping prep_w + gemm1 on the main stream
    cudaEventRecord(g_ss.ev_fork, 0);
    cudaStreamWaitEvent(s2, g_ss.ev_fork, 0);
    zero_deg_kernel<<<zeroBlocks, 1024, 0, s2>>>();
    hist_kernel<<<edgeBlocks, 256, 0, s2>>>(ei);
    csr_bsum_kernel<<<NB, 1024, 0, s2>>>();
    csr_scanb_kernel<<<1, 128, 0, s2>>>();
    csr_offsets_kernel<<<NB, 1024, 0, s2>>>();
    csr_scatter_kernel<<<edgeBlocks, 256, 0, s2>>>(ei);
    cudaEventRecord(g_ss.ev_join, s2);

    // main stream: weights + layer-1 GEMM
    prep_w_kernel<<<dim3(4, 4, 8), dim3(32, 8)>>>(Wq1, Wk1, Wv1, Ws1,
                                                  Wq2, Wk2, Wv2, Ws2);
    gemm_all_kernel<<<GEMM_GRID, 256, smemBytes>>>(0, x, nullptr,
        bq1, bk1, bv1, bs1, qp, khp, vhp, skp);

    // join: attn needs CSR + gemm1
    cudaStreamWaitEvent(0, g_ss.ev_join, 0);
    node_attn_kernel<<<nodeBlocks, 256>>>(qp, khp, vhp, skp, nullptr, a,
                                          nullptr, xtp);

    gemm_all_kernel<<<GEMM_GRID, 256, smemBytes>>>(4, nullptr, xtp,
        bq2, bk2, bv2, bs2, qp, khp, vhp, skp);
    node_attn_kernel<<<nodeBlocks, 256>>>(qp, khp, vhp, skp, x, a,
                                          out, nullptr);
}